// round 8
// baseline (speedup 1.0000x reference)
#include <cuda_runtime.h>
#include <cstdint>

#define B_ 16
#define N_ 577
#define H_ 12
#define D_ 64
#define C_ 768
#define BH_ 192
#define M_ 9232
#define KTS 640       // vT row stride (zero-padded cols 577..639)
#define SST 640       // score row stride
#define SCALE_ 0.125f

// ---------------- device scratch (no cudaMalloc allowed) ----------------
__device__ float g_q[BH_ * N_ * D_];                 // (bh, n, d)
__device__ float g_k[BH_ * N_ * D_];                 // (bh, n, d)
__device__ float g_vT[BH_ * D_ * KTS];               // (bh, d, m) zero-padded
__device__ float g_S[(size_t)(BH_ * N_ + 64) * SST]; // scores, then exp(P)
__device__ float g_pxy[BH_ * N_ * 104];              // px[0:52), py[52:104)
__device__ float g_bins[BH_ * N_ * 104];             // binx[0:52), biny[52:104)
__device__ float g_rowsum[BH_ * N_ + 64];
__device__ float g_ao[M_ * C_];                      // attention out (b*n, c)

// ---------------- tf32 / async helpers (base sm_103 target) ----------------
__device__ __forceinline__ uint32_t f2tf(float f) {
  uint32_t r;
  asm("cvt.rna.tf32.f32 %0, %1;" : "=r"(r) : "f"(f));
  return r;
}
__device__ __forceinline__ void mma16n8k8(float* d, const uint32_t* a,
                                          uint32_t b0, uint32_t b1) {
  asm volatile(
      "mma.sync.aligned.m16n8k8.row.col.f32.tf32.tf32.f32 "
      "{%0,%1,%2,%3}, {%4,%5,%6,%7}, {%8,%9}, {%0,%1,%2,%3};"
      : "+f"(d[0]), "+f"(d[1]), "+f"(d[2]), "+f"(d[3])
      : "r"(a[0]), "r"(a[1]), "r"(a[2]), "r"(a[3]), "r"(b0), "r"(b1));
}
__device__ __forceinline__ uint32_t smem_u32(const void* p) {
  uint32_t a;
  asm("{ .reg .u64 t; cvta.to.shared.u64 t, %1; cvt.u32.u64 %0, t; }"
      : "=r"(a) : "l"(p));
  return a;
}
__device__ __forceinline__ void cp16(uint32_t dst, const void* src, int szbytes) {
  asm volatile("cp.async.cg.shared.global [%0], [%1], 16, %2;" ::"r"(dst),
               "l"(src), "r"(szbytes));
}
__device__ __forceinline__ void cp_commit() {
  asm volatile("cp.async.commit_group;" ::: "memory");
}
template <int NN>
__device__ __forceinline__ void cp_wait() {
  asm volatile("cp.async.wait_group %0;" ::"n"(NN) : "memory");
}
// convert 4 staged fp32 values to tf32 in place
__device__ __forceinline__ void cvt4(uint32_t* p) {
  float4 v = *(const float4*)p;
  *(uint4*)p = make_uint4(f2tf(v.x), f2tf(v.y), f2tf(v.z), f2tf(v.w));
}

// ======== pipelined tf32 mma.sync GEMM: C[m,c] = sum_k A[m,k]*W[c,k] ========
// 128x128 CTA tile, 256 threads, BK=32, 2-stage cp.async + in-place tf32 cvt.
#define MG_SMEM (4 * 128 * 36 * 4)  // A[2][128][36] + B[2][128][36]

template <int MODE>
__global__ __launch_bounds__(256)
void mma_gemm_kernel(const float* __restrict__ Ain, const float* __restrict__ W,
                     float* __restrict__ out) {
  extern __shared__ uint32_t smu[];
  const uint32_t smb = smem_u32(smu);
  const float* A = (MODE == 0) ? Ain : (const float*)g_ao;
  const int row0 = blockIdx.y * 128, col0 = blockIdx.x * 128;
  const int tid = threadIdx.x, lane = tid & 31, wid = tid >> 5;
  const int warpM = wid & 3, warpN = wid >> 2;
  const int g = lane >> 2, tg = lane & 3;

  float acc[16][4];
#pragma unroll
  for (int i = 0; i < 16; i++)
#pragma unroll
    for (int j = 0; j < 4; j++) acc[i][j] = 0.f;

  const int lr = tid >> 1;           // 0..127
  const int lkq = (tid & 1) * 16;    // 0 / 16
  const int asz = ((row0 + lr) < M_) ? 16 : 0;
  const float* ap = A + (size_t)(row0 + lr) * C_ + lkq;
  const float* bp = W + (size_t)(col0 + lr) * C_ + lkq;
  const uint32_t soff = (uint32_t)(lr * 36 + lkq);   // element offset in buffer

  // prefetch tile 0 into buffer 0
#pragma unroll
  for (int i = 0; i < 4; i++) {
    cp16(smb + (soff + i * 4) * 4, ap + i * 4, asz);
    cp16(smb + (9216 + soff + i * 4) * 4, bp + i * 4, 16);
  }
  cp_commit();

  const int NT = C_ / 32;  // 24
  for (int kt = 0; kt < NT; kt++) {
    const int buf = kt & 1;
    if (kt < NT - 1) {
      const int nb = (kt + 1) & 1;
      const float* an = ap + (kt + 1) * 32;
      const float* bn = bp + (kt + 1) * 32;
#pragma unroll
      for (int i = 0; i < 4; i++) {
        cp16(smb + (nb * 4608 + soff + i * 4) * 4, an + i * 4, asz);
        cp16(smb + (9216 + nb * 4608 + soff + i * 4) * 4, bn + i * 4, 16);
      }
      cp_commit();
      cp_wait<1>();
    } else {
      cp_wait<0>();
    }
    __syncthreads();
    // in-place tf32 convert of this thread's staged region
    uint32_t* Ab = smu + buf * 4608;
    uint32_t* Bb = smu + 9216 + buf * 4608;
#pragma unroll
    for (int i = 0; i < 4; i++) {
      cvt4(Ab + soff + i * 4);
      cvt4(Bb + soff + i * 4);
    }
    __syncthreads();
#pragma unroll
    for (int s = 0; s < 4; s++) {
      const int kk = s * 8;
      uint32_t a[2][4];
#pragma unroll
      for (int mt = 0; mt < 2; mt++) {
        const int r = warpM * 32 + mt * 16;
        a[mt][0] = Ab[(r + g) * 36 + kk + tg];
        a[mt][1] = Ab[(r + g + 8) * 36 + kk + tg];
        a[mt][2] = Ab[(r + g) * 36 + kk + tg + 4];
        a[mt][3] = Ab[(r + g + 8) * 36 + kk + tg + 4];
      }
#pragma unroll
      for (int nt = 0; nt < 8; nt++) {
        const int c = warpN * 64 + nt * 8;
        uint32_t b0 = Bb[(c + g) * 36 + kk + tg];
        uint32_t b1 = Bb[(c + g) * 36 + kk + tg + 4];
        mma16n8k8(acc[nt], a[0], b0, b1);
        mma16n8k8(acc[8 + nt], a[1], b0, b1);
      }
    }
    __syncthreads();
  }

  if (MODE == 1) {
#pragma unroll
    for (int mt = 0; mt < 2; mt++)
#pragma unroll
      for (int half = 0; half < 2; half++) {
        const int m = row0 + warpM * 32 + mt * 16 + g + half * 8;
        if (m >= M_) continue;
        float* dst = out + (size_t)m * C_ + col0 + warpN * 64 + 2 * tg;
#pragma unroll
        for (int nt = 0; nt < 8; nt++)
          *(float2*)(dst + nt * 8) = make_float2(acc[mt * 8 + nt][half * 2],
                                                 acc[mt * 8 + nt][half * 2 + 1]);
      }
  } else {
    const int cg = col0 + warpN * 64;   // multiple of 64 -> one head per warp
    const int which = cg / C_;          // 0=q 1=k 2=v
    const int h = (cg % C_) / D_;
#pragma unroll
    for (int mt = 0; mt < 2; mt++)
#pragma unroll
      for (int half = 0; half < 2; half++) {
        const int m = row0 + warpM * 32 + mt * 16 + g + half * 8;
        if (m >= M_) continue;
        const int b = m / N_, n = m % N_;
        const int bh = b * H_ + h;
        if (which == 2) {
          const size_t base = (size_t)bh * D_ * KTS + n;
          const int d0 = 2 * tg;
#pragma unroll
          for (int nt = 0; nt < 8; nt++) {
            g_vT[base + (size_t)(d0 + nt * 8) * KTS] = acc[mt * 8 + nt][half * 2];
            g_vT[base + (size_t)(d0 + nt * 8 + 1) * KTS] =
                acc[mt * 8 + nt][half * 2 + 1];
          }
        } else {
          float* dst = (which == 0 ? g_q : g_k) + ((size_t)bh * N_ + n) * D_ + 2 * tg;
#pragma unroll
          for (int nt = 0; nt < 8; nt++)
            *(float2*)(dst + nt * 8) =
                make_float2(acc[mt * 8 + nt][half * 2],
                            acc[mt * 8 + nt][half * 2 + 1]);
        }
      }
  }
}

// ---------------- px/py projection ----------------
__global__ __launch_bounds__(256)
void pxpy_kernel(const float* __restrict__ qxe, const float* __restrict__ qye) {
  __shared__ float qs[64][65];
  __shared__ float ex[50][33];
  __shared__ float ey[50][33];
  const int bh = blockIdx.y;
  const int row0 = blockIdx.x * 64;
  const int tid = threadIdx.x;
  for (int f = tid; f < 64 * 16; f += 256) {
    int r = f >> 4, c4 = (f & 15) << 2;
    int n = row0 + r;
    float4 v = (n < N_) ? *(const float4*)(g_q + ((size_t)bh * N_ + n) * D_ + c4)
                        : make_float4(0.f, 0.f, 0.f, 0.f);
    qs[r][c4 + 0] = v.x; qs[r][c4 + 1] = v.y;
    qs[r][c4 + 2] = v.z; qs[r][c4 + 3] = v.w;
  }
  for (int f = tid; f < 1600; f += 256) {
    ex[f >> 5][f & 31] = qxe[f];
    ey[f >> 5][f & 31] = qye[f];
  }
  __syncthreads();
  for (int idx = tid; idx < 64 * 50; idx += 256) {
    int r = idx / 50, t = idx % 50;
    float ax = 0.f, ay = 0.f;
#pragma unroll
    for (int d = 0; d < 32; d++) {
      ax += qs[r][d] * ex[t][d];
      ay += qs[r][32 + d] * ey[t][d];
    }
    int n = row0 + r;
    if (n < N_) {
      float* p = g_pxy + ((size_t)bh * N_ + n) * 104;
      p[t] = ax;
      p[52 + t] = ay;
    }
  }
}

// ---------------- scores via mma: S[bh,n,m] = q·k ----------------
// K=64: prefetch both 32-chunks with cp.async, single compute phase.
#define SC_SMEM (4 * 128 * 36 * 4)
__global__ __launch_bounds__(256)
void scores_mma_kernel() {
  extern __shared__ uint32_t smu[];
  const uint32_t smb = smem_u32(smu);
  const int bh = blockIdx.z;
  const int row0 = blockIdx.y * 128, col0 = blockIdx.x * 128;
  const int tid = threadIdx.x, lane = tid & 31, wid = tid >> 5;
  const int warpM = wid & 3, warpN = wid >> 2;
  const int g = lane >> 2, tg = lane & 3;

  float acc[16][4];
#pragma unroll
  for (int i = 0; i < 16; i++)
#pragma unroll
    for (int j = 0; j < 4; j++) acc[i][j] = 0.f;

  const int lr = tid >> 1;
  const int lkq = (tid & 1) * 16;
  const int asz = ((row0 + lr) < N_) ? 16 : 0;
  const int bsz = ((col0 + lr) < N_) ? 16 : 0;
  const float* ap = g_q + ((size_t)bh * N_ + row0 + lr) * D_ + lkq;
  const float* bp = g_k + ((size_t)bh * N_ + col0 + lr) * D_ + lkq;
  const uint32_t soff = (uint32_t)(lr * 36 + lkq);

#pragma unroll
  for (int ch = 0; ch < 2; ch++) {
#pragma unroll
    for (int i = 0; i < 4; i++) {
      cp16(smb + (ch * 4608 + soff + i * 4) * 4, ap + ch * 32 + i * 4, asz);
      cp16(smb + (9216 + ch * 4608 + soff + i * 4) * 4, bp + ch * 32 + i * 4, bsz);
    }
  }
  cp_commit();
  cp_wait<0>();
  __syncthreads();
#pragma unroll
  for (int ch = 0; ch < 2; ch++)
#pragma unroll
    for (int i = 0; i < 4; i++) {
      cvt4(smu + ch * 4608 + soff + i * 4);
      cvt4(smu + 9216 + ch * 4608 + soff + i * 4);
    }
  __syncthreads();

#pragma unroll
  for (int s = 0; s < 8; s++) {
    const int ch = s >> 2, kk = (s & 3) * 8;
    const uint32_t* Ab = smu + ch * 4608;
    const uint32_t* Bb = smu + 9216 + ch * 4608;
    uint32_t a[2][4];
#pragma unroll
    for (int mt = 0; mt < 2; mt++) {
      const int r = warpM * 32 + mt * 16;
      a[mt][0] = Ab[(r + g) * 36 + kk + tg];
      a[mt][1] = Ab[(r + g + 8) * 36 + kk + tg];
      a[mt][2] = Ab[(r + g) * 36 + kk + tg + 4];
      a[mt][3] = Ab[(r + g + 8) * 36 + kk + tg + 4];
    }
#pragma unroll
    for (int nt = 0; nt < 8; nt++) {
      const int c = warpN * 64 + nt * 8;
      uint32_t b0 = Bb[(c + g) * 36 + kk + tg];
      uint32_t b1 = Bb[(c + g) * 36 + kk + tg + 4];
      mma16n8k8(acc[nt], a[0], b0, b1);
      mma16n8k8(acc[8 + nt], a[1], b0, b1);
    }
  }

#pragma unroll
  for (int mt = 0; mt < 2; mt++)
#pragma unroll
    for (int half = 0; half < 2; half++) {
      const int n = row0 + warpM * 32 + mt * 16 + g + half * 8;
      if (n >= N_) continue;
      float* dst = g_S + ((size_t)bh * N_ + n) * SST + col0 + warpN * 64 + 2 * tg;
#pragma unroll
      for (int nt = 0; nt < 8; nt++)
        *(float2*)(dst + nt * 8) = make_float2(acc[mt * 8 + nt][half * 2],
                                               acc[mt * 8 + nt][half * 2 + 1]);
    }
}

// ---------------- softmax + bias + analytic binning ----------------
__global__ __launch_bounds__(256)
void softmax_kernel() {
  __shared__ float st[8][64];
  const int w = threadIdx.x >> 5, lane = threadIdx.x & 31;
  const int row = blockIdx.x * 8 + w;
  if (row >= BH_ * N_) return;
  const int n = row % N_;
  float* Srow = g_S + (size_t)row * SST;
  const float* pxy = g_pxy + (size_t)row * 104;
  const bool cls = (n == 0);
  const int xcol = cls ? 0 : (n - 1) % 24;
  const int yrow = cls ? 0 : (n - 1) / 24;

  float pxl = 0.f, pyl = 0.f;
  if (lane < 24) {
    pxl = cls ? pxy[0] : pxy[25 + lane - xcol];
    pyl = cls ? pxy[52] : pxy[52 + 25 + lane - yrow];
  }
  const float l0 = (Srow[0] + pxy[0] + pxy[52]) * SCALE_;
  float mx = l0;
  float lg[24];
#pragma unroll
  for (int k = 0; k < 24; k++) {
    float pyk = __shfl_sync(0xffffffffu, pyl, k);
    float s = -1e30f;
    if (lane < 24) s = (Srow[1 + 24 * k + lane] + pxl + pyk) * SCALE_;
    lg[k] = s;
    mx = fmaxf(mx, s);
  }
#pragma unroll
  for (int o = 16; o; o >>= 1) mx = fmaxf(mx, __shfl_xor_sync(0xffffffffu, mx, o));

  float colsum = 0.f, total = 0.f, binyreg = 0.f;
  const float e0 = __expf(l0 - mx);
#pragma unroll
  for (int k = 0; k < 24; k++) {
    float e = 0.f;
    if (lane < 24) {
      e = __expf(lg[k] - mx);
      Srow[1 + 24 * k + lane] = e;
    }
    colsum += e;
    float rs = e;
#pragma unroll
    for (int o = 16; o; o >>= 1) rs += __shfl_xor_sync(0xffffffffu, rs, o);
    total += rs;
    if (lane == k) binyreg = rs;
  }
  if (lane == 0) Srow[0] = e0;
  Srow[577 + lane] = 0.f;  // zero-pad cols 577..608 for the AV mma
  total += e0;
  if (lane == 0) g_rowsum[row] = total;

  st[w][lane] = colsum;
  st[w][32 + lane] = binyreg;
  __syncwarp();
  float* brow = g_bins + (size_t)row * 104;
  for (int t = lane; t < 104; t += 32) {
    float v = 0.f;
    if (cls) {
      if (t == 0 || t == 52) v = total;
    } else if (t == 0 || t == 52) {
      v = e0;
    } else if (t < 52) {
      int c = t - 25 + xcol;
      if (c >= 0 && c < 24) v = st[w][c];
    } else {
      int k = (t - 52) - 25 + yrow;
      if (k >= 0 && k < 24) v = st[w][32 + k];
    }
    brow[t] = v;
  }
}

// ---------------- AV via mma (pipelined) + bias-mma + normalize ----------------
#define AV_SMEM 77312
__global__ __launch_bounds__(256)
void av_mma_kernel(const float* __restrict__ vxe, const float* __restrict__ vye) {
  extern __shared__ uint32_t dsm[];
  const uint32_t smb = smem_u32(dsm);
  const int bh = blockIdx.y, row0 = blockIdx.x * 128;
  const int tid = threadIdx.x, lane = tid & 31, wid = tid >> 5;
  const int g = lane >> 2, tg = lane & 3;

  float acc[8][4];
#pragma unroll
  for (int i = 0; i < 8; i++)
#pragma unroll
    for (int j = 0; j < 4; j++) acc[i][j] = 0.f;

  const int lr = tid >> 1, lk = (tid & 1) * 16;
  const float* ap = g_S + ((size_t)bh * N_ + row0 + lr) * SST + lk;
  const int vr = tid >> 2, vc = (tid & 3) * 8;
  const float* vp = g_vT + (size_t)bh * D_ * KTS + (size_t)vr * KTS + vc;
  const int wr = wid * 16;
  const uint32_t aoff = (uint32_t)(lr * 36 + lk);
  const uint32_t boff = (uint32_t)(9216 + vr * 36 + vc);

  // prefetch tile 0
#pragma unroll
  for (int i = 0; i < 4; i++) cp16(smb + (aoff + i * 4) * 4, ap + i * 4, 16);
#pragma unroll
  for (int i = 0; i < 2; i++) cp16(smb + (boff + i * 4) * 4, vp + i * 4, 16);
  cp_commit();

  const int NT = 19;  // 608 / 32
  for (int kt = 0; kt < NT; kt++) {
    const int buf = kt & 1;
    if (kt < NT - 1) {
      const int nb = (kt + 1) & 1;
      const float* an = ap + (kt + 1) * 32;
      const float* vn = vp + (kt + 1) * 32;
#pragma unroll
      for (int i = 0; i < 4; i++)
        cp16(smb + (nb * 4608 + aoff + i * 4) * 4, an + i * 4, 16);
#pragma unroll
      for (int i = 0; i < 2; i++)
        cp16(smb + (nb * 2304 + boff + i * 4) * 4, vn + i * 4, 16);
      cp_commit();
      cp_wait<1>();
    } else {
      cp_wait<0>();
    }
    __syncthreads();
    uint32_t* Ab = dsm + buf * 4608;
    uint32_t* Bb = dsm + 9216 + buf * 2304;
#pragma unroll
    for (int i = 0; i < 4; i++) cvt4(Ab + aoff + i * 4);
#pragma unroll
    for (int i = 0; i < 2; i++) cvt4(dsm + buf * 2304 + boff + i * 4);
    __syncthreads();
#pragma unroll
    for (int s = 0; s < 4; s++) {
      const int kk = s * 8;
      uint32_t a[4];
      a[0] = Ab[(wr + g) * 36 + kk + tg];
      a[1] = Ab[(wr + g + 8) * 36 + kk + tg];
      a[2] = Ab[(wr + g) * 36 + kk + tg + 4];
      a[3] = Ab[(wr + g + 8) * 36 + kk + tg + 4];
#pragma unroll
      for (int nt = 0; nt < 8; nt++) {
        uint32_t b0 = Bb[(nt * 8 + g) * 36 + kk + tg];
        uint32_t b1 = Bb[(nt * 8 + g) * 36 + kk + tg + 4];
        mma16n8k8(acc[nt], a, b0, b1);
      }
    }
    __syncthreads();
  }

  // ---- bias phase: bins (128x52) x emb^T (32x52) accumulated via mma ----
  uint32_t* bxs = dsm;                         // [128][60]
  uint32_t* bys = dsm + 128 * 60;              // [128][60]
  uint32_t* exs = dsm + 2 * 128 * 60;          // [32][60]
  uint32_t* eys = dsm + 2 * 128 * 60 + 32 * 60;
  float* invs = (float*)(dsm + 2 * 128 * 60 + 2 * 32 * 60);  // [128]

  for (int f = tid; f < 128 * 60; f += 256) {
    int r = f / 60, t = f % 60;
    int n = row0 + r;
    float vx = 0.f, vy = 0.f;
    if (t < 52 && n < N_) {
      const float* p = g_bins + ((size_t)bh * N_ + n) * 104;
      vx = p[t];
      vy = p[52 + t];
    }
    bxs[r * 60 + t] = f2tf(vx);
    bys[r * 60 + t] = f2tf(vy);
  }
  for (int f = tid; f < 32 * 60; f += 256) {
    int c = f / 60, t = f % 60;
    float ax = 0.f, ay = 0.f;
    if (t < 50) {
      ax = vxe[t * 32 + c];
      ay = vye[t * 32 + c];
    }
    exs[f] = f2tf(ax);
    eys[f] = f2tf(ay);
  }
  for (int f = tid; f < 128; f += 256) {
    int n = row0 + f;
    invs[f] = (n < N_) ? 1.f / g_rowsum[(size_t)bh * N_ + n] : 1.f;
  }
  __syncthreads();

#pragma unroll
  for (int s = 0; s < 7; s++) {
    const int kk = s * 8;
    uint32_t ax[4], ay[4];
    ax[0] = bxs[(wr + g) * 60 + kk + tg];
    ax[1] = bxs[(wr + g + 8) * 60 + kk + tg];
    ax[2] = bxs[(wr + g) * 60 + kk + tg + 4];
    ax[3] = bxs[(wr + g + 8) * 60 + kk + tg + 4];
    ay[0] = bys[(wr + g) * 60 + kk + tg];
    ay[1] = bys[(wr + g + 8) * 60 + kk + tg];
    ay[2] = bys[(wr + g) * 60 + kk + tg + 4];
    ay[3] = bys[(wr + g + 8) * 60 + kk + tg + 4];
#pragma unroll
    for (int nt = 0; nt < 4; nt++) {
      uint32_t b0 = exs[(nt * 8 + g) * 60 + kk + tg];
      uint32_t b1 = exs[(nt * 8 + g) * 60 + kk + tg + 4];
      mma16n8k8(acc[nt], ax, b0, b1);
    }
#pragma unroll
    for (int nt = 0; nt < 4; nt++) {
      uint32_t b0 = eys[(nt * 8 + g) * 60 + kk + tg];
      uint32_t b1 = eys[(nt * 8 + g) * 60 + kk + tg + 4];
      mma16n8k8(acc[4 + nt], ay, b0, b1);
    }
  }

  // ---- normalize + store ----
  const float i0 = invs[wr + g], i1 = invs[wr + g + 8];
  const int b = bh / H_, h = bh % H_;
#pragma unroll
  for (int half = 0; half < 2; half++) {
    const int n = row0 + wr + g + half * 8;
    if (n >= N_) continue;
    const float inv = half ? i1 : i0;
    float* dst = g_ao + ((size_t)b * N_ + n) * C_ + h * D_ + 2 * tg;
#pragma unroll
    for (int nt = 0; nt < 8; nt++)
      *(float2*)(dst + nt * 8) = make_float2(acc[nt][half * 2] * inv,
                                             acc[nt][half * 2 + 1] * inv);
  }
}

// ---------------- launch ----------------
extern "C" void kernel_launch(void* const* d_in, const int* in_sizes, int n_in,
                              void* d_out, int out_size) {
  const float* x = (const float*)d_in[0];
  const float* qkv_w = (const float*)d_in[1];
  const float* proj_w = (const float*)d_in[2];
  const float* qxe = (const float*)d_in[3];
  const float* qye = (const float*)d_in[4];
  const float* vxe = (const float*)d_in[5];
  const float* vye = (const float*)d_in[6];
  float* out = (float*)d_out;

  cudaFuncSetAttribute(mma_gemm_kernel<0>,
                       cudaFuncAttributeMaxDynamicSharedMemorySize, MG_SMEM);
  cudaFuncSetAttribute(mma_gemm_kernel<1>,
                       cudaFuncAttributeMaxDynamicSharedMemorySize, MG_SMEM);
  cudaFuncSetAttribute(scores_mma_kernel,
                       cudaFuncAttributeMaxDynamicSharedMemorySize, SC_SMEM);
  cudaFuncSetAttribute(av_mma_kernel, cudaFuncAttributeMaxDynamicSharedMemorySize,
                       AV_SMEM);

  // QKV projection (pipelined tf32 tensor cores)
  mma_gemm_kernel<0><<<dim3(18, 73), 256, MG_SMEM>>>(x, qkv_w, nullptr);

  pxpy_kernel<<<dim3(10, BH_), 256>>>(qxe, qye);

  // scores (prefetched tf32 tensor cores)
  scores_mma_kernel<<<dim3(5, 5, BH_), 256, SC_SMEM>>>();

  softmax_kernel<<<(BH_ * N_ + 7) / 8, 256>>>();

  // AV + bias (pipelined tf32 tensor cores)
  av_mma_kernel<<<dim3(5, BH_), 256, AV_SMEM>>>(vxe, vye);

  // Output projection (pipelined tf32 tensor cores)
  mma_gemm_kernel<1><<<dim3(6, 73), 256, MG_SMEM>>>(nullptr, proj_w, out);
}